// round 10
// baseline (speedup 1.0000x reference)
#include <cuda_runtime.h>
#include <cstdint>

// CausalQueue: out[b, 0:C]  = (size == D) ? buffer[head, b, :] : 0
//              out[b, C:2C] = x[b, :]
// x: [B,C] f32, buffer: [D,B,C] f32, size/head int32 device scalars.
// D=128, B=2048, C=512. 16 MB total traffic -> latency/ramp bound.
//
// R8: maximize TLP x MLP in ONE resident wave.
//   grid 512 x 256 thr = 131K threads (all resident: 148 SMs x 2048 cap).
//   Block covers 4 output rows; thread t owns column t of the 256-float4
//   row (t<128 past half, t>=128 x half -> warp-uniform branch).
//   4 independent front-batched loads per thread (MLP_p1=4), then 4 stores.
//   x-half warps never read the scalars.

#define D_CAP  128
#define B_DIM  2048
#define C4     128              // float4 per half-row (C=512)
#define ROW4   256              // float4 per output row
#define RPB    4                // rows per block
#define GRID   (B_DIM / RPB)    // 512

__global__ void __launch_bounds__(256)
causal_queue_kernel(const float4* __restrict__ x,
                    const float4* __restrict__ buffer,
                    const int* __restrict__ size_p,
                    const int* __restrict__ head_p,
                    float4* __restrict__ out)
{
    const int t    = threadIdx.x;        // 0..255 = column in output row
    const int row0 = blockIdx.x * RPB;

    float4 v[RPB];

    if (t < C4) {
        // past half, column t
        const int  head = __ldg(head_p);
        const bool full = (__ldg(size_p) == D_CAP);
        if (full) {
            const float4* src = buffer + (size_t)head * (B_DIM * C4)
                                       + (size_t)row0 * C4 + t;
#pragma unroll
            for (int k = 0; k < RPB; k++) v[k] = src[k * C4];
        } else {
#pragma unroll
            for (int k = 0; k < RPB; k++) v[k] = make_float4(0.f, 0.f, 0.f, 0.f);
        }
    } else {
        // x half, column t-128
        const float4* src = x + (size_t)row0 * C4 + (t - C4);
#pragma unroll
        for (int k = 0; k < RPB; k++) v[k] = src[k * C4];
    }

    float4* dst = out + (size_t)row0 * ROW4 + t;
#pragma unroll
    for (int k = 0; k < RPB; k++) dst[k * ROW4] = v[k];
}

extern "C" void kernel_launch(void* const* d_in, const int* in_sizes, int n_in,
                              void* d_out, int out_size)
{
    const float4* x      = (const float4*)d_in[0];   // [B, C] f32
    const float4* buffer = (const float4*)d_in[1];   // [D, B, C] f32
    const int*    size_p = (const int*)d_in[2];      // scalar
    const int*    head_p = (const int*)d_in[3];      // scalar
    float4*       out    = (float4*)d_out;           // [B, 2C] f32

    causal_queue_kernel<<<GRID, 256>>>(x, buffer, size_p, head_p, out);
}